// round 2
// baseline (speedup 1.0000x reference)
#include <cuda_runtime.h>
#include <cuda_bf16.h>
#include <cstdint>

// Problem constants (fixed by the dataset)
#define N_NODES  100000
#define N_EDGES  1600000
#define N_GRAPHS 2048
#define DIM      128

// -------- scratch (no allocation allowed; __device__ globals) ------------
__device__ __align__(256) float g_agg [N_NODES * DIM];   // GIN accumulator
__device__ __align__(256) float g_t   [N_NODES * DIM];   // MLP hidden / GCN accum
__device__ __align__(256) float g_h   [N_NODES * DIM];   // GIN output h
__device__ __align__(256) float g_deg [N_NODES];
__device__ __align__(256) float g_dinv[N_NODES];
__device__ __align__(256) float g_pool[N_GRAPHS * DIM];

// -------- helpers --------------------------------------------------------
__device__ __forceinline__ void red4(float* p, float4 v) {
    asm volatile("red.global.add.v4.f32 [%0], {%1,%2,%3,%4};"
                 :: "l"(p), "f"(v.x), "f"(v.y), "f"(v.z), "f"(v.w) : "memory");
}

// -------- kernel 1: init  agg=x, deg=1, pool=0 ---------------------------
__global__ void k_init(const float* __restrict__ x) {
    int t = blockIdx.x * blockDim.x + threadIdx.x;      // over float4s of agg
    int total4 = N_NODES * (DIM / 4);                    // 3.2M
    if (t < total4) {
        ((float4*)g_agg)[t] = ((const float4*)x)[t];
    }
    if (t < N_NODES) g_deg[t] = 1.0f;
    if (t < N_GRAPHS * (DIM / 4)) ((float4*)g_pool)[t] = make_float4(0.f, 0.f, 0.f, 0.f);
}

// -------- kernel 2: GIN edge scatter  agg[dst] += x[src], deg[dst]+=1 ----
__global__ void k_scatter_gin(const float* __restrict__ x,
                              const int* __restrict__ ei, int E) {
    int t = blockIdx.x * blockDim.x + threadIdx.x;
    if (t >= E * 32) return;
    int e = t >> 5, lane = t & 31;
    int s = ei[e];
    int d = ei[E + e];
    float4 v = ((const float4*)(x + (size_t)s * DIM))[lane];
    red4(g_agg + (size_t)d * DIM + lane * 4, v);
    if (lane == 0) atomicAdd(g_deg + d, 1.0f);
}

// -------- kernel 3/4/7: tiled fp32 GEMM  Y = relu(X @ W + b) -------------
// Tile: 128(m) x 128(n) x 16(k); 256 threads; 8x8 microtile per thread.
// MODE 0: store Y.  MODE 1: red-add relu(Y) into pool[batch[m]] (fused pooling).
template <int MODE>
__global__ void k_gemm(const float* __restrict__ X, const float* __restrict__ W,
                       const float* __restrict__ bias, float* __restrict__ Y,
                       const int* __restrict__ batch, float* __restrict__ pool,
                       int N) {
    __shared__ float Xs[16][128];
    __shared__ float Ws[16][128];

    const int tid = threadIdx.x;
    const int tx = tid & 15;         // n-group
    const int ty = tid >> 4;         // m-group
    const int m0 = blockIdx.x * 128;

    float acc[8][8];
#pragma unroll
    for (int i = 0; i < 8; i++)
#pragma unroll
        for (int j = 0; j < 8; j++) acc[i][j] = 0.f;

    for (int k0 = 0; k0 < 128; k0 += 16) {
        // --- load X tile (transposed into Xs[k][m]) ---
        {
            int r = tid >> 1;                 // 0..127 tile row
            int ko = (tid & 1) * 8;           // 0 or 8
            int gm = m0 + r;
            float4 a0, a1;
            if (gm < N) {
                const float4* p = (const float4*)(X + (size_t)gm * 128 + k0 + ko);
                a0 = p[0]; a1 = p[1];
            } else {
                a0 = a1 = make_float4(0.f, 0.f, 0.f, 0.f);
            }
            Xs[ko + 0][r] = a0.x; Xs[ko + 1][r] = a0.y;
            Xs[ko + 2][r] = a0.z; Xs[ko + 3][r] = a0.w;
            Xs[ko + 4][r] = a1.x; Xs[ko + 5][r] = a1.y;
            Xs[ko + 6][r] = a1.z; Xs[ko + 7][r] = a1.w;
        }
        // --- load W tile (same layout Ws[k][n]) ---
        {
            int e  = tid * 8;
            int kw = e >> 7;
            int nw = e & 127;
            const float* wp = W + (size_t)(k0 + kw) * 128 + nw;
            float4 w0 = *(const float4*)(wp);
            float4 w1 = *(const float4*)(wp + 4);
            *(float4*)&Ws[kw][nw]     = w0;
            *(float4*)&Ws[kw][nw + 4] = w1;
        }
        __syncthreads();

#pragma unroll
        for (int kk = 0; kk < 16; kk++) {
            float4 xa = *(float4*)&Xs[kk][ty * 8];
            float4 xb = *(float4*)&Xs[kk][ty * 8 + 4];
            float4 wa = *(float4*)&Ws[kk][tx * 8];
            float4 wb = *(float4*)&Ws[kk][tx * 8 + 4];
            float am[8] = {xa.x, xa.y, xa.z, xa.w, xb.x, xb.y, xb.z, xb.w};
            float bn[8] = {wa.x, wa.y, wa.z, wa.w, wb.x, wb.y, wb.z, wb.w};
#pragma unroll
            for (int i = 0; i < 8; i++)
#pragma unroll
                for (int j = 0; j < 8; j++)
                    acc[i][j] = fmaf(am[i], bn[j], acc[i][j]);
        }
        __syncthreads();
    }

    // --- epilogue ---
    const int n0 = tx * 8;
    float b0 = bias[n0 + 0], b1 = bias[n0 + 1], b2 = bias[n0 + 2], b3 = bias[n0 + 3];
    float b4 = bias[n0 + 4], b5 = bias[n0 + 5], b6 = bias[n0 + 6], b7 = bias[n0 + 7];
#pragma unroll
    for (int i = 0; i < 8; i++) {
        int gm = m0 + ty * 8 + i;
        if (gm >= N) continue;
        float4 ya = make_float4(fmaxf(acc[i][0] + b0, 0.f), fmaxf(acc[i][1] + b1, 0.f),
                                fmaxf(acc[i][2] + b2, 0.f), fmaxf(acc[i][3] + b3, 0.f));
        float4 yb = make_float4(fmaxf(acc[i][4] + b4, 0.f), fmaxf(acc[i][5] + b5, 0.f),
                                fmaxf(acc[i][6] + b6, 0.f), fmaxf(acc[i][7] + b7, 0.f));
        if (MODE == 0) {
            float4* yp = (float4*)(Y + (size_t)gm * 128 + n0);
            yp[0] = ya; yp[1] = yb;
        } else {
            int bg = batch[gm];
            float* pp = pool + (size_t)bg * 128 + n0;
            red4(pp, ya);
            red4(pp + 4, yb);
        }
    }
}

// -------- kernel 5: dinv = rsqrt(deg); t = dinv^2 * h (GCN self-loop) ----
__global__ void k_prep_gcn() {
    int t = blockIdx.x * blockDim.x + threadIdx.x;
    if (t >= N_NODES * 32) return;
    int n = t >> 5, lane = t & 31;
    float di = rsqrtf(g_deg[n]);
    if (lane == 0) g_dinv[n] = di;
    float s = di * di;
    float4 h4 = ((const float4*)g_h)[(size_t)n * 32 + lane];
    ((float4*)g_t)[(size_t)n * 32 + lane] =
        make_float4(s * h4.x, s * h4.y, s * h4.z, s * h4.w);
}

// -------- kernel 6: GCN edge scatter  t[dst] += dinv[s]*dinv[d]*h[src] ---
__global__ void k_scatter_gcn(const int* __restrict__ ei, int E) {
    int t = blockIdx.x * blockDim.x + threadIdx.x;
    if (t >= E * 32) return;
    int e = t >> 5, lane = t & 31;
    int s = ei[e];
    int d = ei[E + e];
    float nm = g_dinv[s] * g_dinv[d];
    float4 v = ((const float4*)(g_h + (size_t)s * DIM))[lane];
    v.x *= nm; v.y *= nm; v.z *= nm; v.w *= nm;
    red4(g_t + (size_t)d * DIM + lane * 4, v);
}

// -------- kernel 8: head  out = relu(pool@W1+b1)@W2+b2  ------------------
__global__ void k_head(const float* __restrict__ w1, const float* __restrict__ b1,
                       const float* __restrict__ w2, const float* __restrict__ b2,
                       float* __restrict__ out) {
    __shared__ float gs[128];
    __shared__ float ts[128];
    int g = blockIdx.x;
    int j = threadIdx.x;
    gs[j] = g_pool[(size_t)g * 128 + j];
    __syncthreads();
    float acc = b1[j];
#pragma unroll 8
    for (int k = 0; k < 128; k++) acc = fmaf(gs[k], w1[(size_t)k * 128 + j], acc);
    ts[j] = fmaxf(acc, 0.f);
    __syncthreads();
    if (j < 32) {
        float o0 = 0.f, o1 = 0.f, o2 = 0.f;
#pragma unroll
        for (int k = j; k < 128; k += 32) {
            float tv = ts[k];
            o0 = fmaf(tv, w2[k * 3 + 0], o0);
            o1 = fmaf(tv, w2[k * 3 + 1], o1);
            o2 = fmaf(tv, w2[k * 3 + 2], o2);
        }
#pragma unroll
        for (int off = 16; off; off >>= 1) {
            o0 += __shfl_down_sync(0xffffffffu, o0, off);
            o1 += __shfl_down_sync(0xffffffffu, o1, off);
            o2 += __shfl_down_sync(0xffffffffu, o2, off);
        }
        if (j == 0) {
            out[g * 3 + 0] = o0 + b2[0];
            out[g * 3 + 1] = o1 + b2[1];
            out[g * 3 + 2] = o2 + b2[2];
        }
    }
}

// -------- launcher -------------------------------------------------------
extern "C" void kernel_launch(void* const* d_in, const int* in_sizes, int n_in,
                              void* d_out, int out_size) {
    const float* x      = (const float*)d_in[0];
    const int*   ei     = (const int*)d_in[1];     // JAX default x64-off -> int32
    const int*   batch  = (const int*)d_in[2];     // int32
    const float* gin_w1 = (const float*)d_in[3];
    const float* gin_b1 = (const float*)d_in[4];
    const float* gin_w2 = (const float*)d_in[5];
    const float* gin_b2 = (const float*)d_in[6];
    const float* gcn_w  = (const float*)d_in[7];
    const float* gcn_b  = (const float*)d_in[8];
    const float* lin1_w = (const float*)d_in[9];
    const float* lin1_b = (const float*)d_in[10];
    const float* lin2_w = (const float*)d_in[11];
    const float* lin2_b = (const float*)d_in[12];
    float*       out    = (float*)d_out;

    const int N = in_sizes[0] / DIM;       // 100000
    const int E = in_sizes[1] / 2;         // 1600000

    float* agg_p;  cudaGetSymbolAddress((void**)&agg_p,  g_agg);
    float* t_p;    cudaGetSymbolAddress((void**)&t_p,    g_t);
    float* h_p;    cudaGetSymbolAddress((void**)&h_p,    g_h);
    float* pool_p; cudaGetSymbolAddress((void**)&pool_p, g_pool);

    const int TB = 256;
    int initThreads = N * 32;                                   // covers all init work
    k_init<<<(initThreads + TB - 1) / TB, TB>>>(x);

    int scatterThreads = E * 32;
    k_scatter_gin<<<(scatterThreads + TB - 1) / TB, TB>>>(x, ei, E);

    int gblocks = (N + 127) / 128;
    // t = relu(agg @ gin_w1 + b1)
    k_gemm<0><<<gblocks, 256>>>(agg_p, gin_w1, gin_b1, t_p, nullptr, nullptr, N);
    // h = relu(t @ gin_w2 + b2)   (outer relu of the reference)
    k_gemm<0><<<gblocks, 256>>>(t_p, gin_w2, gin_b2, h_p, nullptr, nullptr, N);

    k_prep_gcn<<<(N * 32 + TB - 1) / TB, TB>>>();
    k_scatter_gcn<<<(scatterThreads + TB - 1) / TB, TB>>>(ei, E);

    // pool[batch] += relu(t @ gcn_w + gcn_b)   (fused GCN GEMM + global_add_pool)
    k_gemm<1><<<gblocks, 256>>>(t_p, gcn_w, gcn_b, nullptr, batch, pool_p, N);

    k_head<<<N_GRAPHS, 128>>>(lin1_w, lin1_b, lin2_w, lin2_b, out);
}

// round 3
// speedup vs baseline: 1.6485x; 1.6485x over previous
#include <cuda_runtime.h>
#include <cuda_bf16.h>
#include <cstdint>

#define N_NODES  100000
#define N_EDGES  1600000
#define N_GRAPHS 2048
#define DIM      128
#define SCAN_B   1024
#define NSCAN    ((N_NODES + SCAN_B - 1) / SCAN_B)   // 98

// -------- scratch --------------------------------------------------------
__device__ __align__(256) float g_agg [N_NODES * DIM];
__device__ __align__(256) float g_t   [N_NODES * DIM];
__device__ __align__(256) float g_h   [N_NODES * DIM];   // holds hs = dinv*h
__device__ __align__(256) float g_dinv[N_NODES];
__device__ __align__(256) float g_pool[N_GRAPHS * DIM];
__device__ __align__(256) int   g_cnt [N_NODES];
__device__ __align__(256) int   g_off [N_NODES];
__device__ __align__(256) int   g_cur [N_NODES];
__device__ __align__(256) int   g_bsum[NSCAN + 1];
__device__ __align__(256) int   g_csr [N_EDGES];

__device__ __forceinline__ void red4(float* p, float4 v) {
    asm volatile("red.global.add.v4.f32 [%0], {%1,%2,%3,%4};"
                 :: "l"(p), "f"(v.x), "f"(v.y), "f"(v.z), "f"(v.w) : "memory");
}

// -------- init: cnt=0, pool=0 --------------------------------------------
__global__ void k_init0() {
    int t = blockIdx.x * blockDim.x + threadIdx.x;
    if (t < N_NODES) g_cnt[t] = 0;
    if (t < N_GRAPHS * (DIM / 4))
        ((float4*)g_pool)[t] = make_float4(0.f, 0.f, 0.f, 0.f);
}

// -------- degree count ---------------------------------------------------
__global__ void k_count(const int* __restrict__ ei, int E) {
    int e = blockIdx.x * blockDim.x + threadIdx.x;
    if (e >= E) return;
    atomicAdd(&g_cnt[ei[E + e]], 1);
}

// -------- prefix scan (3 phases) -----------------------------------------
__global__ void k_scanA() {
    __shared__ int sh[SCAN_B];
    int tid = threadIdx.x;
    int i = blockIdx.x * SCAN_B + tid;
    int v = (i < N_NODES) ? g_cnt[i] : 0;
    sh[tid] = v;
    __syncthreads();
#pragma unroll
    for (int o = 1; o < SCAN_B; o <<= 1) {
        int t = (tid >= o) ? sh[tid - o] : 0;
        __syncthreads();
        sh[tid] += t;
        __syncthreads();
    }
    if (i < N_NODES) g_off[i] = sh[tid] - v;       // exclusive within block
    if (tid == SCAN_B - 1) g_bsum[blockIdx.x] = sh[tid];
}

__global__ void k_scanB() {
    if (threadIdx.x == 0) {
        int acc = 0;
        for (int b = 0; b < NSCAN; b++) {
            int v = g_bsum[b];
            g_bsum[b] = acc;
            acc += v;
        }
    }
}

__global__ void k_scanC() {
    int i = blockIdx.x * blockDim.x + threadIdx.x;
    if (i >= N_NODES) return;
    int off = g_off[i] + g_bsum[i / SCAN_B];
    g_off[i] = off;
    g_cur[i] = off;
    g_dinv[i] = rsqrtf((float)(g_cnt[i] + 1));
}

// -------- CSR fill -------------------------------------------------------
__global__ void k_fill(const int* __restrict__ ei, int E) {
    int e = blockIdx.x * blockDim.x + threadIdx.x;
    if (e >= E) return;
    int s = ei[e];
    int d = ei[E + e];
    int pos = atomicAdd(&g_cur[d], 1);
    g_csr[pos] = s;
}

// -------- pull aggregation: warp per node --------------------------------
// GCN=0: out[n] = feat[n] + sum_{s in N(n)} feat[s]
// GCN=1: out[n] = dinv[n] * (feat[n] + sum feat[s])
template <int GCN>
__global__ void k_pull(const float* __restrict__ feat, float* __restrict__ out) {
    int w = (blockIdx.x * blockDim.x + threadIdx.x) >> 5;
    if (w >= N_NODES) return;
    int lane = threadIdx.x & 31;
    int beg = g_off[w];
    int end = beg + g_cnt[w];
    float4 acc = ((const float4*)(feat + (size_t)w * DIM))[lane];
    for (int i = beg; i < end; i++) {
        int s = g_csr[i];
        float4 v = ((const float4*)(feat + (size_t)s * DIM))[lane];
        acc.x += v.x; acc.y += v.y; acc.z += v.z; acc.w += v.w;
    }
    if (GCN) {
        float di = g_dinv[w];
        acc.x *= di; acc.y *= di; acc.z *= di; acc.w *= di;
    }
    ((float4*)(out + (size_t)w * DIM))[lane] = acc;
}

// -------- tiled fp32 GEMM  Y = relu(X @ W + b) ---------------------------
// MODE 0: store.  MODE 1: red-add into pool[batch[m]].  MODE 2: store dinv[m]*relu.
template <int MODE>
__global__ void k_gemm(const float* __restrict__ X, const float* __restrict__ W,
                       const float* __restrict__ bias, float* __restrict__ Y,
                       const int* __restrict__ batch, float* __restrict__ pool,
                       int N) {
    __shared__ float Xs[16][128];
    __shared__ float Ws[16][128];

    const int tid = threadIdx.x;
    const int tx = tid & 15;
    const int ty = tid >> 4;
    const int m0 = blockIdx.x * 128;

    float acc[8][8];
#pragma unroll
    for (int i = 0; i < 8; i++)
#pragma unroll
        for (int j = 0; j < 8; j++) acc[i][j] = 0.f;

    for (int k0 = 0; k0 < 128; k0 += 16) {
        {
            int r = tid >> 1;
            int ko = (tid & 1) * 8;
            int gm = m0 + r;
            float4 a0, a1;
            if (gm < N) {
                const float4* p = (const float4*)(X + (size_t)gm * 128 + k0 + ko);
                a0 = p[0]; a1 = p[1];
            } else {
                a0 = a1 = make_float4(0.f, 0.f, 0.f, 0.f);
            }
            Xs[ko + 0][r] = a0.x; Xs[ko + 1][r] = a0.y;
            Xs[ko + 2][r] = a0.z; Xs[ko + 3][r] = a0.w;
            Xs[ko + 4][r] = a1.x; Xs[ko + 5][r] = a1.y;
            Xs[ko + 6][r] = a1.z; Xs[ko + 7][r] = a1.w;
        }
        {
            int e  = tid * 8;
            int kw = e >> 7;
            int nw = e & 127;
            const float* wp = W + (size_t)(k0 + kw) * 128 + nw;
            float4 w0 = *(const float4*)(wp);
            float4 w1 = *(const float4*)(wp + 4);
            *(float4*)&Ws[kw][nw]     = w0;
            *(float4*)&Ws[kw][nw + 4] = w1;
        }
        __syncthreads();

#pragma unroll
        for (int kk = 0; kk < 16; kk++) {
            float4 xa = *(float4*)&Xs[kk][ty * 8];
            float4 xb = *(float4*)&Xs[kk][ty * 8 + 4];
            float4 wa = *(float4*)&Ws[kk][tx * 8];
            float4 wb = *(float4*)&Ws[kk][tx * 8 + 4];
            float am[8] = {xa.x, xa.y, xa.z, xa.w, xb.x, xb.y, xb.z, xb.w};
            float bn[8] = {wa.x, wa.y, wa.z, wa.w, wb.x, wb.y, wb.z, wb.w};
#pragma unroll
            for (int i = 0; i < 8; i++)
#pragma unroll
                for (int j = 0; j < 8; j++)
                    acc[i][j] = fmaf(am[i], bn[j], acc[i][j]);
        }
        __syncthreads();
    }

    const int n0 = tx * 8;
    float b0 = bias[n0 + 0], b1 = bias[n0 + 1], b2 = bias[n0 + 2], b3 = bias[n0 + 3];
    float b4 = bias[n0 + 4], b5 = bias[n0 + 5], b6 = bias[n0 + 6], b7 = bias[n0 + 7];
#pragma unroll
    for (int i = 0; i < 8; i++) {
        int gm = m0 + ty * 8 + i;
        if (gm >= N) continue;
        float sc = (MODE == 2) ? g_dinv[gm] : 1.0f;
        float4 ya = make_float4(sc * fmaxf(acc[i][0] + b0, 0.f), sc * fmaxf(acc[i][1] + b1, 0.f),
                                sc * fmaxf(acc[i][2] + b2, 0.f), sc * fmaxf(acc[i][3] + b3, 0.f));
        float4 yb = make_float4(sc * fmaxf(acc[i][4] + b4, 0.f), sc * fmaxf(acc[i][5] + b5, 0.f),
                                sc * fmaxf(acc[i][6] + b6, 0.f), sc * fmaxf(acc[i][7] + b7, 0.f));
        if (MODE == 1) {
            int bg = batch[gm];
            float* pp = pool + (size_t)bg * 128 + n0;
            red4(pp, ya);
            red4(pp + 4, yb);
        } else {
            float4* yp = (float4*)(Y + (size_t)gm * 128 + n0);
            yp[0] = ya; yp[1] = yb;
        }
    }
}

// -------- head -----------------------------------------------------------
__global__ void k_head(const float* __restrict__ w1, const float* __restrict__ b1,
                       const float* __restrict__ w2, const float* __restrict__ b2,
                       float* __restrict__ out) {
    __shared__ float gs[128];
    __shared__ float ts[128];
    int g = blockIdx.x;
    int j = threadIdx.x;
    gs[j] = g_pool[(size_t)g * 128 + j];
    __syncthreads();
    float acc = b1[j];
#pragma unroll 8
    for (int k = 0; k < 128; k++) acc = fmaf(gs[k], w1[(size_t)k * 128 + j], acc);
    ts[j] = fmaxf(acc, 0.f);
    __syncthreads();
    if (j < 32) {
        float o0 = 0.f, o1 = 0.f, o2 = 0.f;
#pragma unroll
        for (int k = j; k < 128; k += 32) {
            float tv = ts[k];
            o0 = fmaf(tv, w2[k * 3 + 0], o0);
            o1 = fmaf(tv, w2[k * 3 + 1], o1);
            o2 = fmaf(tv, w2[k * 3 + 2], o2);
        }
#pragma unroll
        for (int off = 16; off; off >>= 1) {
            o0 += __shfl_down_sync(0xffffffffu, o0, off);
            o1 += __shfl_down_sync(0xffffffffu, o1, off);
            o2 += __shfl_down_sync(0xffffffffu, o2, off);
        }
        if (j == 0) {
            out[g * 3 + 0] = o0 + b2[0];
            out[g * 3 + 1] = o1 + b2[1];
            out[g * 3 + 2] = o2 + b2[2];
        }
    }
}

// -------- launcher -------------------------------------------------------
extern "C" void kernel_launch(void* const* d_in, const int* in_sizes, int n_in,
                              void* d_out, int out_size) {
    const float* x      = (const float*)d_in[0];
    const int*   ei     = (const int*)d_in[1];
    const int*   batch  = (const int*)d_in[2];
    const float* gin_w1 = (const float*)d_in[3];
    const float* gin_b1 = (const float*)d_in[4];
    const float* gin_w2 = (const float*)d_in[5];
    const float* gin_b2 = (const float*)d_in[6];
    const float* gcn_w  = (const float*)d_in[7];
    const float* gcn_b  = (const float*)d_in[8];
    const float* lin1_w = (const float*)d_in[9];
    const float* lin1_b = (const float*)d_in[10];
    const float* lin2_w = (const float*)d_in[11];
    const float* lin2_b = (const float*)d_in[12];
    float*       out    = (float*)d_out;

    const int N = in_sizes[0] / DIM;       // 100000
    const int E = in_sizes[1] / 2;         // 1600000

    float* agg_p;  cudaGetSymbolAddress((void**)&agg_p,  g_agg);
    float* t_p;    cudaGetSymbolAddress((void**)&t_p,    g_t);
    float* h_p;    cudaGetSymbolAddress((void**)&h_p,    g_h);
    float* pool_p; cudaGetSymbolAddress((void**)&pool_p, g_pool);

    const int TB = 256;

    // CSR build
    k_init0<<<(N + TB - 1) / TB, TB>>>();
    k_count<<<(E + TB - 1) / TB, TB>>>(ei, E);
    k_scanA<<<NSCAN, SCAN_B>>>();
    k_scanB<<<1, 32>>>();
    k_scanC<<<(N + TB - 1) / TB, TB>>>();
    k_fill<<<(E + TB - 1) / TB, TB>>>(ei, E);

    int pblocks = (N * 32 + TB - 1) / TB;
    // GIN aggregate (pull): agg = x + sum x[src]
    k_pull<0><<<pblocks, TB>>>(x, agg_p);

    int gblocks = (N + 127) / 128;
    // t = relu(agg @ gin_w1 + b1)
    k_gemm<0><<<gblocks, 256>>>(agg_p, gin_w1, gin_b1, t_p, nullptr, nullptr, N);
    // hs = dinv * relu(t @ gin_w2 + b2)
    k_gemm<2><<<gblocks, 256>>>(t_p, gin_w2, gin_b2, h_p, nullptr, nullptr, N);

    // GCN aggregate (pull): t = dinv * (hs + sum hs[src])
    k_pull<1><<<pblocks, TB>>>(h_p, t_p);

    // pool[batch] += relu(t @ gcn_w + gcn_b)
    k_gemm<1><<<gblocks, 256>>>(t_p, gcn_w, gcn_b, nullptr, batch, pool_p, N);

    k_head<<<N_GRAPHS, 128>>>(lin1_w, lin1_b, lin2_w, lin2_b, out);
}

// round 4
// speedup vs baseline: 2.2537x; 1.3672x over previous
#include <cuda_runtime.h>
#include <cuda_bf16.h>
#include <cstdint>

#define N_NODES  100000
#define N_EDGES  1600000
#define N_GRAPHS 2048
#define DIM      128
#define SCAN_B   1024
#define NSCAN    ((N_NODES + SCAN_B - 1) / SCAN_B)   // 98

// -------- scratch --------------------------------------------------------
__device__ __align__(256) float g_agg [N_NODES * DIM];
__device__ __align__(256) float g_t   [N_NODES * DIM];
__device__ __align__(256) float g_h   [N_NODES * DIM];
__device__ __align__(256) float g_dinv[N_NODES];
__device__ __align__(256) float g_pool[N_GRAPHS * DIM];
__device__ __align__(256) int   g_cnt [N_NODES];
__device__ __align__(256) int   g_off [N_NODES];
__device__ __align__(256) int   g_cur [N_NODES];
__device__ __align__(256) int   g_bsum[NSCAN + 1];
__device__ __align__(256) int   g_csr [N_EDGES];

__device__ __forceinline__ void red2(float* p, float a, float b) {
    asm volatile("red.global.add.v2.f32 [%0], {%1,%2};"
                 :: "l"(p), "f"(a), "f"(b) : "memory");
}
__device__ __forceinline__ float tf32r(float x) {
    float y;
    asm("cvt.rna.tf32.f32 %0, %1;" : "=f"(y) : "f"(x));
    return y;
}

// -------- init: cnt=0, pool=0 --------------------------------------------
__global__ void k_init0() {
    int t = blockIdx.x * blockDim.x + threadIdx.x;
    if (t < N_NODES) g_cnt[t] = 0;
    if (t < N_GRAPHS * (DIM / 4))
        ((float4*)g_pool)[t] = make_float4(0.f, 0.f, 0.f, 0.f);
}

// -------- degree count ---------------------------------------------------
__global__ void k_count(const int* __restrict__ ei, int E) {
    int e = blockIdx.x * blockDim.x + threadIdx.x;
    if (e >= E) return;
    atomicAdd(&g_cnt[ei[E + e]], 1);
}

// -------- prefix scan ----------------------------------------------------
__global__ void k_scanA() {
    __shared__ int sh[SCAN_B];
    int tid = threadIdx.x;
    int i = blockIdx.x * SCAN_B + tid;
    int v = (i < N_NODES) ? g_cnt[i] : 0;
    sh[tid] = v;
    __syncthreads();
#pragma unroll
    for (int o = 1; o < SCAN_B; o <<= 1) {
        int t = (tid >= o) ? sh[tid - o] : 0;
        __syncthreads();
        sh[tid] += t;
        __syncthreads();
    }
    if (i < N_NODES) g_off[i] = sh[tid] - v;
    if (tid == SCAN_B - 1) g_bsum[blockIdx.x] = sh[tid];
}

__global__ void k_scanB() {                 // parallel scan over NSCAN block sums
    __shared__ int sh[128];
    int tid = threadIdx.x;
    int v = (tid < NSCAN) ? g_bsum[tid] : 0;
    sh[tid] = v;
    __syncthreads();
#pragma unroll
    for (int o = 1; o < 128; o <<= 1) {
        int t = (tid >= o) ? sh[tid - o] : 0;
        __syncthreads();
        sh[tid] += t;
        __syncthreads();
    }
    if (tid < NSCAN) g_bsum[tid] = sh[tid] - v;   // exclusive
}

__global__ void k_scanC() {
    int i = blockIdx.x * blockDim.x + threadIdx.x;
    if (i >= N_NODES) return;
    int off = g_off[i] + g_bsum[i / SCAN_B];
    g_off[i] = off;
    g_cur[i] = off;
    g_dinv[i] = rsqrtf((float)(g_cnt[i] + 1));
}

// -------- CSR fill -------------------------------------------------------
__global__ void k_fill(const int* __restrict__ ei, int E) {
    int e = blockIdx.x * blockDim.x + threadIdx.x;
    if (e >= E) return;
    int s = ei[e];
    int d = ei[E + e];
    int pos = atomicAdd(&g_cur[d], 1);
    g_csr[pos] = s;
}

// -------- pull aggregation: warp per node --------------------------------
template <int GCN>
__global__ void k_pull(const float* __restrict__ feat, float* __restrict__ out) {
    int w = (blockIdx.x * blockDim.x + threadIdx.x) >> 5;
    if (w >= N_NODES) return;
    int lane = threadIdx.x & 31;
    int beg = g_off[w];
    int end = beg + g_cnt[w];
    float4 acc = ((const float4*)(feat + (size_t)w * DIM))[lane];
    for (int i = beg; i < end; i++) {
        int s = g_csr[i];
        float4 v = ((const float4*)(feat + (size_t)s * DIM))[lane];
        acc.x += v.x; acc.y += v.y; acc.z += v.z; acc.w += v.w;
    }
    if (GCN) {
        float di = g_dinv[w];
        acc.x *= di; acc.y *= di; acc.z *= di; acc.w *= di;
    }
    ((float4*)(out + (size_t)w * DIM))[lane] = acc;
}

// -------- TF32 tensor-core GEMM  Y = relu(X @ W + b) ---------------------
// Block tile 128(m) x 128(n), K = 128 in 4 chunks of 32. 8 warps, each 64x32.
// MODE 0: store.  MODE 1: red-add into pool[batch[m]].  MODE 2: store dinv[m]*relu.
#define XS_STRIDE 136
template <int MODE>
__global__ __launch_bounds__(256, 2)
void k_gemm_tc(const float* __restrict__ X, const float* __restrict__ W,
               const float* __restrict__ bias, float* __restrict__ Y,
               const int* __restrict__ batch, float* __restrict__ pool, int N) {
    __shared__ float Xs[32 * XS_STRIDE];    // [k][m], tf32-rounded
    __shared__ float Ws[32 * XS_STRIDE];    // [k][n], tf32-rounded

    const int tid  = threadIdx.x;
    const int lane = tid & 31;
    const int wid  = tid >> 5;              // 0..7
    const int wm   = wid & 1;               // m half (0/1) -> rows wm*64
    const int wn   = wid >> 1;              // 0..3        -> cols wn*32
    const int g    = lane >> 2;             // 0..7
    const int c    = lane & 3;              // 0..3
    const int m0   = blockIdx.x * 128;

    float acc[4][4][4];
#pragma unroll
    for (int mi = 0; mi < 4; mi++)
#pragma unroll
        for (int ni = 0; ni < 4; ni++)
#pragma unroll
            for (int q = 0; q < 4; q++) acc[mi][ni][q] = 0.f;

    for (int kb = 0; kb < 128; kb += 32) {
        // load X[m0..+127][kb..+31] -> Xs[k][m] (transposed, tf32)
        {
            int r = tid >> 1;               // 0..127
            int h = (tid & 1) * 16;         // 0 or 16
            int gm = m0 + r;
            const float4* p = (const float4*)(X + (size_t)gm * 128 + kb + h);
#pragma unroll
            for (int j = 0; j < 4; j++) {
                float4 v = (gm < N) ? p[j] : make_float4(0.f, 0.f, 0.f, 0.f);
                int k = h + j * 4;
                Xs[(k + 0) * XS_STRIDE + r] = tf32r(v.x);
                Xs[(k + 1) * XS_STRIDE + r] = tf32r(v.y);
                Xs[(k + 2) * XS_STRIDE + r] = tf32r(v.z);
                Xs[(k + 3) * XS_STRIDE + r] = tf32r(v.w);
            }
        }
        // load W[kb..+31][0..127] -> Ws[k][n] (tf32)
        {
            int kw = tid >> 3;              // 0..31
            int nc = (tid & 7) * 16;        // 0..112
            const float4* wp = (const float4*)(W + (size_t)(kb + kw) * 128 + nc);
            float* dst = &Ws[kw * XS_STRIDE + nc];
#pragma unroll
            for (int j = 0; j < 4; j++) {
                float4 v = wp[j];
                float4 o = make_float4(tf32r(v.x), tf32r(v.y), tf32r(v.z), tf32r(v.w));
                *(float4*)(dst + j * 4) = o;
            }
        }
        __syncthreads();

#pragma unroll
        for (int ks = 0; ks < 4; ks++) {
            const int k8 = ks * 8;
            // A fragments for 4 m16 tiles
            uint32_t a[4][4];
#pragma unroll
            for (int mi = 0; mi < 4; mi++) {
                int mrow = wm * 64 + mi * 16 + g;
                a[mi][0] = __float_as_uint(Xs[(k8 + c) * XS_STRIDE + mrow]);
                a[mi][1] = __float_as_uint(Xs[(k8 + c) * XS_STRIDE + mrow + 8]);
                a[mi][2] = __float_as_uint(Xs[(k8 + c + 4) * XS_STRIDE + mrow]);
                a[mi][3] = __float_as_uint(Xs[(k8 + c + 4) * XS_STRIDE + mrow + 8]);
            }
            // B fragments for 4 n8 tiles
            uint32_t b[4][2];
#pragma unroll
            for (int ni = 0; ni < 4; ni++) {
                int ncol = wn * 32 + ni * 8 + g;
                b[ni][0] = __float_as_uint(Ws[(k8 + c) * XS_STRIDE + ncol]);
                b[ni][1] = __float_as_uint(Ws[(k8 + c + 4) * XS_STRIDE + ncol]);
            }
#pragma unroll
            for (int mi = 0; mi < 4; mi++)
#pragma unroll
                for (int ni = 0; ni < 4; ni++) {
                    asm volatile(
                        "mma.sync.aligned.m16n8k8.row.col.f32.tf32.tf32.f32 "
                        "{%0,%1,%2,%3}, {%4,%5,%6,%7}, {%8,%9}, {%0,%1,%2,%3};"
                        : "+f"(acc[mi][ni][0]), "+f"(acc[mi][ni][1]),
                          "+f"(acc[mi][ni][2]), "+f"(acc[mi][ni][3])
                        : "r"(a[mi][0]), "r"(a[mi][1]), "r"(a[mi][2]), "r"(a[mi][3]),
                          "r"(b[ni][0]), "r"(b[ni][1]));
                }
        }
        __syncthreads();
    }

    // -------- epilogue --------
#pragma unroll
    for (int ni = 0; ni < 4; ni++) {
        int col = wn * 32 + ni * 8 + 2 * c;
        float bb0 = bias[col], bb1 = bias[col + 1];
#pragma unroll
        for (int mi = 0; mi < 4; mi++) {
            int r0 = m0 + wm * 64 + mi * 16 + g;
            int r1 = r0 + 8;
            float sc0 = 1.f, sc1 = 1.f;
            if (MODE == 2) {
                if (r0 < N) sc0 = g_dinv[r0];
                if (r1 < N) sc1 = g_dinv[r1];
            }
            float y00 = sc0 * fmaxf(acc[mi][ni][0] + bb0, 0.f);
            float y01 = sc0 * fmaxf(acc[mi][ni][1] + bb1, 0.f);
            float y10 = sc1 * fmaxf(acc[mi][ni][2] + bb0, 0.f);
            float y11 = sc1 * fmaxf(acc[mi][ni][3] + bb1, 0.f);
            if (MODE == 1) {
                if (r0 < N) red2(pool + (size_t)batch[r0] * 128 + col, y00, y01);
                if (r1 < N) red2(pool + (size_t)batch[r1] * 128 + col, y10, y11);
            } else {
                if (r0 < N) *(float2*)(Y + (size_t)r0 * 128 + col) = make_float2(y00, y01);
                if (r1 < N) *(float2*)(Y + (size_t)r1 * 128 + col) = make_float2(y10, y11);
            }
        }
    }
}

// -------- head -----------------------------------------------------------
__global__ void k_head(const float* __restrict__ w1, const float* __restrict__ b1,
                       const float* __restrict__ w2, const float* __restrict__ b2,
                       float* __restrict__ out) {
    __shared__ float gs[128];
    __shared__ float ts[128];
    int g = blockIdx.x;
    int j = threadIdx.x;
    gs[j] = g_pool[(size_t)g * 128 + j];
    __syncthreads();
    float acc = b1[j];
#pragma unroll 8
    for (int k = 0; k < 128; k++) acc = fmaf(gs[k], w1[(size_t)k * 128 + j], acc);
    ts[j] = fmaxf(acc, 0.f);
    __syncthreads();
    if (j < 32) {
        float o0 = 0.f, o1 = 0.f, o2 = 0.f;
#pragma unroll
        for (int k = j; k < 128; k += 32) {
            float tv = ts[k];
            o0 = fmaf(tv, w2[k * 3 + 0], o0);
            o1 = fmaf(tv, w2[k * 3 + 1], o1);
            o2 = fmaf(tv, w2[k * 3 + 2], o2);
        }
#pragma unroll
        for (int off = 16; off; off >>= 1) {
            o0 += __shfl_down_sync(0xffffffffu, o0, off);
            o1 += __shfl_down_sync(0xffffffffu, o1, off);
            o2 += __shfl_down_sync(0xffffffffu, o2, off);
        }
        if (j == 0) {
            out[g * 3 + 0] = o0 + b2[0];
            out[g * 3 + 1] = o1 + b2[1];
            out[g * 3 + 2] = o2 + b2[2];
        }
    }
}

// -------- launcher -------------------------------------------------------
extern "C" void kernel_launch(void* const* d_in, const int* in_sizes, int n_in,
                              void* d_out, int out_size) {
    const float* x      = (const float*)d_in[0];
    const int*   ei     = (const int*)d_in[1];
    const int*   batch  = (const int*)d_in[2];
    const float* gin_w1 = (const float*)d_in[3];
    const float* gin_b1 = (const float*)d_in[4];
    const float* gin_w2 = (const float*)d_in[5];
    const float* gin_b2 = (const float*)d_in[6];
    const float* gcn_w  = (const float*)d_in[7];
    const float* gcn_b  = (const float*)d_in[8];
    const float* lin1_w = (const float*)d_in[9];
    const float* lin1_b = (const float*)d_in[10];
    const float* lin2_w = (const float*)d_in[11];
    const float* lin2_b = (const float*)d_in[12];
    float*       out    = (float*)d_out;

    const int N = in_sizes[0] / DIM;       // 100000
    const int E = in_sizes[1] / 2;         // 1600000

    float* agg_p;  cudaGetSymbolAddress((void**)&agg_p,  g_agg);
    float* t_p;    cudaGetSymbolAddress((void**)&t_p,    g_t);
    float* h_p;    cudaGetSymbolAddress((void**)&h_p,    g_h);
    float* pool_p; cudaGetSymbolAddress((void**)&pool_p, g_pool);

    const int TB = 256;

    // CSR build
    k_init0<<<(N + TB - 1) / TB, TB>>>();
    k_count<<<(E + TB - 1) / TB, TB>>>(ei, E);
    k_scanA<<<NSCAN, SCAN_B>>>();
    k_scanB<<<1, 128>>>();
    k_scanC<<<(N + TB - 1) / TB, TB>>>();
    k_fill<<<(E + TB - 1) / TB, TB>>>(ei, E);

    int pblocks = (N * 32 + TB - 1) / TB;
    // GIN aggregate (pull): agg = x + sum x[src]
    k_pull<0><<<pblocks, TB>>>(x, agg_p);

    int gblocks = (N + 127) / 128;
    // t = relu(agg @ gin_w1 + b1)
    k_gemm_tc<0><<<gblocks, 256>>>(agg_p, gin_w1, gin_b1, t_p, nullptr, nullptr, N);
    // hs = dinv * relu(t @ gin_w2 + b2)
    k_gemm_tc<2><<<gblocks, 256>>>(t_p, gin_w2, gin_b2, h_p, nullptr, nullptr, N);

    // GCN aggregate (pull): t = dinv * (hs + sum hs[src])
    k_pull<1><<<pblocks, TB>>>(h_p, t_p);

    // pool[batch] += relu(t @ gcn_w + gcn_b)
    k_gemm_tc<1><<<gblocks, 256>>>(t_p, gcn_w, gcn_b, nullptr, batch, pool_p, N);

    k_head<<<N_GRAPHS, 128>>>(lin1_w, lin1_b, lin2_w, lin2_b, out);
}

// round 7
// speedup vs baseline: 2.5135x; 1.1153x over previous
#include <cuda_runtime.h>
#include <cuda_bf16.h>
#include <cstdint>

#define N_NODES  100000
#define N_EDGES  1600000
#define N_GRAPHS 2048
#define DIM      128
#define SCAN_B   1024
#define NSCAN    ((N_NODES + SCAN_B - 1) / SCAN_B)   // 98

// -------- scratch --------------------------------------------------------
__device__ __align__(256) float g_agg [N_NODES * DIM];
__device__ __align__(256) float g_t   [N_NODES * DIM];
__device__ __align__(256) float g_h   [N_NODES * DIM];
__device__ __align__(256) float g_dinv[N_NODES];
__device__ __align__(256) float g_pool[N_GRAPHS * DIM];
__device__ __align__(256) float g_wr  [3 * DIM * DIM];     // tf32-rounded weights
__device__ __align__(256) int   g_cnt [N_NODES];
__device__ __align__(256) int   g_off [N_NODES];
__device__ __align__(256) int   g_cur [N_NODES];
__device__ __align__(256) int   g_bsum[NSCAN + 2];
__device__ __align__(256) int   g_csr [N_EDGES];

__device__ __forceinline__ void red4(float* p, float4 v) {
    asm volatile("red.global.add.v4.f32 [%0], {%1,%2,%3,%4};"
                 :: "l"(p), "f"(v.x), "f"(v.y), "f"(v.z), "f"(v.w) : "memory");
}
__device__ __forceinline__ float tf32r(float x) {
    float y;
    asm("cvt.rna.tf32.f32 %0, %1;" : "=f"(y) : "f"(x));
    return y;
}
__device__ __forceinline__ uint32_t smem_u32(const void* p) {
    uint32_t a;
    asm("{ .reg .u64 t; cvta.to.shared.u64 t, %1; cvt.u32.u64 %0, t; }" : "=r"(a) : "l"(p));
    return a;
}
__device__ __forceinline__ void cp16(uint32_t dst, const void* src, uint32_t nbytes) {
    asm volatile("cp.async.cg.shared.global [%0], [%1], 16, %2;"
                 :: "r"(dst), "l"(src), "r"(nbytes) : "memory");
}

// ======== CSR build ======================================================
__global__ void k_init0() {
    int t = blockIdx.x * blockDim.x + threadIdx.x;
    if (t < N_NODES) g_cnt[t] = 0;
    if (t < N_GRAPHS * (DIM / 4))
        ((float4*)g_pool)[t] = make_float4(0.f, 0.f, 0.f, 0.f);
}

__global__ void k_count(const int* __restrict__ ei, int E) {
    int e = blockIdx.x * blockDim.x + threadIdx.x;
    if (e >= E) return;
    atomicAdd(&g_cnt[ei[E + e]], 1);
}

__global__ void k_scanA() {
    __shared__ int sh[SCAN_B];
    int tid = threadIdx.x;
    int i = blockIdx.x * SCAN_B + tid;
    int v = (i < N_NODES) ? g_cnt[i] : 0;
    sh[tid] = v;
    __syncthreads();
#pragma unroll
    for (int o = 1; o < SCAN_B; o <<= 1) {
        int t = (tid >= o) ? sh[tid - o] : 0;
        __syncthreads();
        sh[tid] += t;
        __syncthreads();
    }
    if (i < N_NODES) g_off[i] = sh[tid] - v;
    if (tid == SCAN_B - 1) g_bsum[blockIdx.x] = sh[tid];
}

// scanC: each block redundantly scans the 98 block sums, then finalizes.
__global__ void k_scanC() {
    __shared__ int sh[256];
    int tid = threadIdx.x;
    int v = (tid < NSCAN) ? g_bsum[tid] : 0;
    sh[tid] = v;
    __syncthreads();
#pragma unroll
    for (int o = 1; o < 256; o <<= 1) {
        int t = (tid >= o) ? sh[tid - o] : 0;
        __syncthreads();
        sh[tid] += t;
        __syncthreads();
    }
    int inc = sh[tid];
    __syncthreads();
    sh[tid] = inc - v;          // exclusive
    __syncthreads();
    int i = blockIdx.x * blockDim.x + tid;
    if (i >= N_NODES) return;
    int off = g_off[i] + sh[i / SCAN_B];
    g_off[i] = off;
    g_cur[i] = off;
    g_dinv[i] = rsqrtf((float)(g_cnt[i] + 1));
}

__global__ void k_fill(const int* __restrict__ ei, int E) {
    int e = blockIdx.x * blockDim.x + threadIdx.x;
    if (e >= E) return;
    int s = ei[e];
    int d = ei[E + e];
    int pos = atomicAdd(&g_cur[d], 1);
    g_csr[pos] = s;
}

// ======== weight tf32-rounding (one-shot) ================================
__global__ void k_round_w(const float* __restrict__ w1, const float* __restrict__ w2,
                          const float* __restrict__ w3) {
    int i = blockIdx.x * blockDim.x + threadIdx.x;
    if (i >= 3 * DIM * DIM) return;
    int z = i / (DIM * DIM);
    int r = i - z * DIM * DIM;
    const float* src = (z == 0) ? w1 : (z == 1) ? w2 : w3;
    g_wr[i] = tf32r(src[r]);
}

// ======== pull aggregation: warp per node (tf32-rounded output) ==========
template <int GCN>
__global__ void k_pull(const float* __restrict__ feat, float* __restrict__ out) {
    int w = (blockIdx.x * blockDim.x + threadIdx.x) >> 5;
    if (w >= N_NODES) return;
    int lane = threadIdx.x & 31;
    int beg = g_off[w];
    int end = beg + g_cnt[w];
    float4 acc = ((const float4*)(feat + (size_t)w * DIM))[lane];
    for (int i = beg; i < end; i++) {
        int s = g_csr[i];
        float4 v = ((const float4*)(feat + (size_t)s * DIM))[lane];
        acc.x += v.x; acc.y += v.y; acc.z += v.z; acc.w += v.w;
    }
    if (GCN) {
        float di = g_dinv[w];
        acc.x *= di; acc.y *= di; acc.z *= di; acc.w *= di;
    }
    acc.x = tf32r(acc.x); acc.y = tf32r(acc.y);
    acc.z = tf32r(acc.z); acc.w = tf32r(acc.w);
    ((float4*)(out + (size_t)w * DIM))[lane] = acc;
}

// ======== pipelined tf32 mma.sync GEMM  Y = relu(X @ W + b) ==============
// 128m x 128n block, K=128 in 4 chunks of 32, cp.async double-buffered.
// 8 warps: wm=wid&1 (64 rows), wn=wid>>1 (32 cols). A via ldmatrix (swizzled
// row-major), B scalar LDS at stride 136 (bank-clean).
// MODE 0: store tf32r.  MODE 1: red-add into pool[batch[m]].  MODE 2: tf32r(dinv*relu).
#define A_BYTES 16384           // 128 rows x 32 floats
#define B_WORDS (32 * 136)      // k x n, stride 136
#define B_BYTES (B_WORDS * 4)   // 17408
#define OFF_A0  0
#define OFF_A1  A_BYTES
#define OFF_B0  (2 * A_BYTES)
#define OFF_B1  (2 * A_BYTES + B_BYTES)
#define SMEM_TOT (2 * A_BYTES + 2 * B_BYTES)   // 67584

template <int MODE>
__global__ __launch_bounds__(256, 2)
void k_gemm(const float* __restrict__ X, const float* __restrict__ W,
            const float* __restrict__ bias, float* __restrict__ Y,
            const int* __restrict__ batch, float* __restrict__ pool, int N) {
    extern __shared__ char sm[];
    const uint32_t smb = smem_u32(sm);
    const int tid  = threadIdx.x;
    const int lane = tid & 31;
    const int wid  = tid >> 5;
    const int wm   = wid & 1;
    const int wn   = wid >> 1;
    const int g    = lane >> 2;
    const int c    = lane & 3;
    const int m0   = blockIdx.x * 128;

    // ---- staging helpers (each thread moves 4x16B per operand) ----
    auto stage = [&](int buf, int kb) {
        uint32_t a_dst = smb + (buf ? OFF_A1 : OFF_A0);
        uint32_t b_dst = smb + (buf ? OFF_B1 : OFF_B0);
#pragma unroll
        for (int j = 0; j < 4; j++) {
            int idx = tid * 4 + j;            // 0..1023
            int r = idx >> 3, ch = idx & 7;   // row, 16B-chunk
            int gm = m0 + r;
            uint32_t d = a_dst + r * 128 + ((ch ^ (r & 7)) << 4);
            const float* s = X + (size_t)gm * DIM + kb + ch * 4;
            cp16(d, s, (gm < N) ? 16u : 0u);
        }
#pragma unroll
        for (int j = 0; j < 4; j++) {
            int idx = tid * 4 + j;            // 0..1023
            int kw = idx >> 5, nc = (idx & 31) * 4;
            uint32_t d = b_dst + (kw * 136 + nc) * 4;
            const float* s = W + (size_t)(kb + kw) * DIM + nc;
            cp16(d, s, 16u);
        }
        asm volatile("cp.async.commit_group;" ::: "memory");
    };

    float acc[4][4][4];
#pragma unroll
    for (int mi = 0; mi < 4; mi++)
#pragma unroll
        for (int ni = 0; ni < 4; ni++)
#pragma unroll
            for (int q = 0; q < 4; q++) acc[mi][ni][q] = 0.f;

    stage(0, 0);

#pragma unroll
    for (int it = 0; it < 4; it++) {
        if (it < 3) stage((it + 1) & 1, (it + 1) * 32);
        if (it < 3) asm volatile("cp.async.wait_group 1;" ::: "memory");
        else        asm volatile("cp.async.wait_group 0;" ::: "memory");
        __syncthreads();

        const int buf = it & 1;
        const uint32_t abase = smb + (buf ? OFF_A1 : OFF_A0);
        const uint32_t* Bp = (const uint32_t*)(sm + (buf ? OFF_B1 : OFF_B0));

#pragma unroll
        for (int ks = 0; ks < 4; ks++) {
            uint32_t a[4][4];
#pragma unroll
            for (int mi = 0; mi < 4; mi++) {
                int sub = lane >> 3, lrow = lane & 7;
                int r = wm * 64 + mi * 16 + lrow + (sub & 1) * 8;
                int ch = ks * 2 + (sub >> 1);
                uint32_t addr = abase + r * 128 + ((ch ^ (r & 7)) << 4);
                asm volatile(
                    "ldmatrix.sync.aligned.m8n8.x4.shared.b16 {%0,%1,%2,%3}, [%4];"
                    : "=r"(a[mi][0]), "=r"(a[mi][1]), "=r"(a[mi][2]), "=r"(a[mi][3])
                    : "r"(addr));
            }
            uint32_t b[4][2];
            const int k8 = ks * 8;
#pragma unroll
            for (int ni = 0; ni < 4; ni++) {
                int ncol = wn * 32 + ni * 8 + g;
                b[ni][0] = Bp[(k8 + c) * 136 + ncol];
                b[ni][1] = Bp[(k8 + c + 4) * 136 + ncol];
            }
#pragma unroll
            for (int mi = 0; mi < 4; mi++)
#pragma unroll
                for (int ni = 0; ni < 4; ni++) {
                    asm volatile(
                        "mma.sync.aligned.m16n8k8.row.col.f32.tf32.tf32.f32 "
                        "{%0,%1,%2,%3}, {%4,%5,%6,%7}, {%8,%9}, {%0,%1,%2,%3};"
                        : "+f"(acc[mi][ni][0]), "+f"(acc[mi][ni][1]),
                          "+f"(acc[mi][ni][2]), "+f"(acc[mi][ni][3])
                        : "r"(a[mi][0]), "r"(a[mi][1]), "r"(a[mi][2]), "r"(a[mi][3]),
                          "r"(b[ni][0]), "r"(b[ni][1]));
                }
        }
        __syncthreads();
    }

    // -------- epilogue --------
#pragma unroll
    for (int ni = 0; ni < 4; ni++) {
        int col = wn * 32 + ni * 8 + 2 * c;
        float bb0 = bias[col], bb1 = bias[col + 1];
#pragma unroll
        for (int mi = 0; mi < 4; mi++) {
            int r0 = m0 + wm * 64 + mi * 16 + g;
            int r1 = r0 + 8;
            float sc0 = 1.f, sc1 = 1.f;
            if (MODE == 2) {
                if (r0 < N) sc0 = g_dinv[r0];
                if (r1 < N) sc1 = g_dinv[r1];
            }
            float y00 = sc0 * fmaxf(acc[mi][ni][0] + bb0, 0.f);
            float y01 = sc0 * fmaxf(acc[mi][ni][1] + bb1, 0.f);
            float y10 = sc1 * fmaxf(acc[mi][ni][2] + bb0, 0.f);
            float y11 = sc1 * fmaxf(acc[mi][ni][3] + bb1, 0.f);
            if (MODE == 1) {
                if (r0 < N) {
                    float* pp = pool + (size_t)batch[r0] * 128 + col;
                    asm volatile("red.global.add.v2.f32 [%0], {%1,%2};"
                                 :: "l"(pp), "f"(y00), "f"(y01) : "memory");
                }
                if (r1 < N) {
                    float* pp = pool + (size_t)batch[r1] * 128 + col;
                    asm volatile("red.global.add.v2.f32 [%0], {%1,%2};"
                                 :: "l"(pp), "f"(y10), "f"(y11) : "memory");
                }
            } else {
                if (r0 < N) *(float2*)(Y + (size_t)r0 * 128 + col) =
                    make_float2(tf32r(y00), tf32r(y01));
                if (r1 < N) *(float2*)(Y + (size_t)r1 * 128 + col) =
                    make_float2(tf32r(y10), tf32r(y11));
            }
        }
    }
}

// ======== head ===========================================================
__global__ void k_head(const float* __restrict__ w1, const float* __restrict__ b1,
                       const float* __restrict__ w2, const float* __restrict__ b2,
                       float* __restrict__ out) {
    __shared__ float gs[128];
    __shared__ float ts[128];
    int g = blockIdx.x;
    int j = threadIdx.x;
    gs[j] = g_pool[(size_t)g * 128 + j];
    __syncthreads();
    float acc = b1[j];
#pragma unroll 8
    for (int k = 0; k < 128; k++) acc = fmaf(gs[k], w1[(size_t)k * 128 + j], acc);
    ts[j] = fmaxf(acc, 0.f);
    __syncthreads();
    if (j < 32) {
        float o0 = 0.f, o1 = 0.f, o2 = 0.f;
#pragma unroll
        for (int k = j; k < 128; k += 32) {
            float tv = ts[k];
            o0 = fmaf(tv, w2[k * 3 + 0], o0);
            o1 = fmaf(tv, w2[k * 3 + 1], o1);
            o2 = fmaf(tv, w2[k * 3 + 2], o2);
        }
#pragma unroll
        for (int off = 16; off; off >>= 1) {
            o0 += __shfl_down_sync(0xffffffffu, o0, off);
            o1 += __shfl_down_sync(0xffffffffu, o1, off);
            o2 += __shfl_down_sync(0xffffffffu, o2, off);
        }
        if (j == 0) {
            out[g * 3 + 0] = o0 + b2[0];
            out[g * 3 + 1] = o1 + b2[1];
            out[g * 3 + 2] = o2 + b2[2];
        }
    }
}

// ======== launcher =======================================================
extern "C" void kernel_launch(void* const* d_in, const int* in_sizes, int n_in,
                              void* d_out, int out_size) {
    const float* x      = (const float*)d_in[0];
    const int*   ei     = (const int*)d_in[1];
    const int*   batch  = (const int*)d_in[2];
    const float* gin_w1 = (const float*)d_in[3];
    const float* gin_b1 = (const float*)d_in[4];
    const float* gin_w2 = (const float*)d_in[5];
    const float* gin_b2 = (const float*)d_in[6];
    const float* gcn_w  = (const float*)d_in[7];
    const float* gcn_b  = (const float*)d_in[8];
    const float* lin1_w = (const float*)d_in[9];
    const float* lin1_b = (const float*)d_in[10];
    const float* lin2_w = (const float*)d_in[11];
    const float* lin2_b = (const float*)d_in[12];
    float*       out    = (float*)d_out;

    const int N = in_sizes[0] / DIM;       // 100000
    const int E = in_sizes[1] / 2;         // 1600000

    float* agg_p;  cudaGetSymbolAddress((void**)&agg_p,  g_agg);
    float* t_p;    cudaGetSymbolAddress((void**)&t_p,    g_t);
    float* h_p;    cudaGetSymbolAddress((void**)&h_p,    g_h);
    float* pool_p; cudaGetSymbolAddress((void**)&pool_p, g_pool);
    float* wr_p;   cudaGetSymbolAddress((void**)&wr_p,   g_wr);

    static bool attr_done = false;
    if (!attr_done) {
        cudaFuncSetAttribute(k_gemm<0>, cudaFuncAttributeMaxDynamicSharedMemorySize, SMEM_TOT);
        cudaFuncSetAttribute(k_gemm<1>, cudaFuncAttributeMaxDynamicSharedMemorySize, SMEM_TOT);
        cudaFuncSetAttribute(k_gemm<2>, cudaFuncAttributeMaxDynamicSharedMemorySize, SMEM_TOT);
        attr_done = true;
    }

    const int TB = 256;

    // CSR build (ordered so the ncu capture lands on k_pull<0>)
    k_init0<<<(N + TB - 1) / TB, TB>>>();
    k_count<<<(E + TB - 1) / TB, TB>>>(ei, E);
    k_scanA<<<NSCAN, SCAN_B>>>();
    k_scanC<<<(N + TB - 1) / TB, TB>>>();
    k_fill<<<(E + TB - 1) / TB, TB>>>(ei, E);

    int pblocks = (N * 32 + TB - 1) / TB;
    // GIN aggregate (pull): agg = tf32r(x + sum x[src])
    k_pull<0><<<pblocks, TB>>>(x, agg_p);

    // tf32-round the three GEMM weights
    k_round_w<<<(3 * DIM * DIM + TB - 1) / TB, TB>>>(gin_w1, gin_w2, gcn_w);

    int gblocks = (N + 127) / 128;          // 782
    // t = tf32r(relu(agg @ gin_w1 + b1))
    k_gemm<0><<<gblocks, 256, SMEM_TOT>>>(agg_p, wr_p + 0 * DIM * DIM, gin_b1, t_p,
                                          nullptr, nullptr, N);
    // hs = tf32r(dinv * relu(t @ gin_w2 + b2))
    k_gemm<2><<<gblocks, 256, SMEM_TOT>>>(t_p, wr_p + 1 * DIM * DIM, gin_b2, h_p,
                                          nullptr, nullptr, N);

    // GCN aggregate (pull): t = tf32r(dinv * (hs + sum hs[src]))
    k_pull<1><<<pblocks, TB>>>(h_p, t_p);

    // pool[batch] += relu(t @ gcn_w + gcn_b)
    k_gemm<1><<<gblocks, 256, SMEM_TOT>>>(t_p, wr_p + 2 * DIM * DIM, gcn_b, nullptr,
                                          batch, pool_p, N);

    k_head<<<N_GRAPHS, 128>>>(lin1_w, lin1_b, lin2_w, lin2_b, out);
}

// round 9
// speedup vs baseline: 2.6157x; 1.0407x over previous
#include <cuda_runtime.h>
#include <cuda_bf16.h>
#include <cstdint>

#define N_NODES  100000
#define N_EDGES  1600000
#define N_GRAPHS 2048
#define DIM      128
#define SCAN_B   1024
#define NSCAN    ((N_NODES + SCAN_B - 1) / SCAN_B)   // 98

// -------- scratch --------------------------------------------------------
__device__ __align__(256) float g_agg [N_NODES * DIM];
__device__ __align__(256) float g_t   [N_NODES * DIM];
__device__ __align__(256) float g_h   [N_NODES * DIM];
__device__ __align__(256) float g_dinv[N_NODES];
__device__ __align__(256) float g_pool[N_GRAPHS * DIM];
__device__ __align__(256) float g_wr  [3 * DIM * DIM];     // tf32-rounded weights
__device__ __align__(256) int   g_cnt [N_NODES];
__device__ __align__(256) int   g_off [N_NODES];
__device__ __align__(256) int   g_cur [N_NODES];
__device__ __align__(256) int   g_bsum[NSCAN + 2];
__device__ __align__(256) int   g_csr [N_EDGES];

__device__ __forceinline__ float tf32r(float x) {
    float y;
    asm("cvt.rna.tf32.f32 %0, %1;" : "=f"(y) : "f"(x));
    return y;
}
__device__ __forceinline__ uint32_t smem_u32(const void* p) {
    uint32_t a;
    asm("{ .reg .u64 t; cvta.to.shared.u64 t, %1; cvt.u32.u64 %0, t; }" : "=r"(a) : "l"(p));
    return a;
}
__device__ __forceinline__ void cp16(uint32_t dst, const void* src, uint32_t nbytes) {
    asm volatile("cp.async.cg.shared.global [%0], [%1], 16, %2;"
                 :: "r"(dst), "l"(src), "r"(nbytes) : "memory");
}

// ======== CSR build ======================================================
__global__ void k_count(const int* __restrict__ ei, int E) {
    int e = blockIdx.x * blockDim.x + threadIdx.x;
    if (e >= E) return;
    atomicAdd(&g_cnt[ei[E + e]], 1);
}

__global__ void k_scanA() {
    __shared__ int sh[SCAN_B];
    int tid = threadIdx.x;
    int i = blockIdx.x * SCAN_B + tid;
    int v = (i < N_NODES) ? g_cnt[i] : 0;
    sh[tid] = v;
    __syncthreads();
#pragma unroll
    for (int o = 1; o < SCAN_B; o <<= 1) {
        int t = (tid >= o) ? sh[tid - o] : 0;
        __syncthreads();
        sh[tid] += t;
        __syncthreads();
    }
    if (i < N_NODES) g_off[i] = sh[tid] - v;
    if (tid == SCAN_B - 1) g_bsum[blockIdx.x] = sh[tid];
}

// scanC: each block redundantly scans the 98 block sums, then finalizes.
__global__ void k_scanC() {
    __shared__ int sh[256];
    int tid = threadIdx.x;
    int v = (tid < NSCAN) ? g_bsum[tid] : 0;
    sh[tid] = v;
    __syncthreads();
#pragma unroll
    for (int o = 1; o < 256; o <<= 1) {
        int t = (tid >= o) ? sh[tid - o] : 0;
        __syncthreads();
        sh[tid] += t;
        __syncthreads();
    }
    int inc = sh[tid];
    __syncthreads();
    sh[tid] = inc - v;          // exclusive
    __syncthreads();
    int i = blockIdx.x * blockDim.x + tid;
    if (i >= N_NODES) return;
    int off = g_off[i] + sh[i / SCAN_B];
    g_off[i] = off;
    g_cur[i] = off;
    g_dinv[i] = rsqrtf((float)(g_cnt[i] + 1));
}

__global__ void k_fill(const int* __restrict__ ei, int E) {
    int e = blockIdx.x * blockDim.x + threadIdx.x;
    if (e >= E) return;
    int s = ei[e];
    int d = ei[E + e];
    int pos = atomicAdd(&g_cur[d], 1);
    g_csr[pos] = s;
}

// ======== weight tf32-rounding (one-shot) ================================
__global__ void k_round_w(const float* __restrict__ w1, const float* __restrict__ w2,
                          const float* __restrict__ w3) {
    int i = blockIdx.x * blockDim.x + threadIdx.x;
    if (i >= 3 * DIM * DIM) return;
    int z = i / (DIM * DIM);
    int r = i - z * DIM * DIM;
    const float* src = (z == 0) ? w1 : (z == 1) ? w2 : w3;
    g_wr[i] = tf32r(src[r]);
}

// ======== pull aggregation: warp per node, MLP-4 unrolled ================
template <int GCN>
__global__ void k_pull(const float* __restrict__ feat, float* __restrict__ out) {
    int w = (blockIdx.x * blockDim.x + threadIdx.x) >> 5;
    if (w >= N_NODES) return;
    int lane = threadIdx.x & 31;
    int beg = g_off[w];
    int end = beg + g_cnt[w];
    float4 acc = ((const float4*)(feat + (size_t)w * DIM))[lane];
    int i = beg;
    for (; i + 4 <= end; i += 4) {
        int s0 = g_csr[i], s1 = g_csr[i + 1], s2 = g_csr[i + 2], s3 = g_csr[i + 3];
        float4 v0 = ((const float4*)(feat + (size_t)s0 * DIM))[lane];
        float4 v1 = ((const float4*)(feat + (size_t)s1 * DIM))[lane];
        float4 v2 = ((const float4*)(feat + (size_t)s2 * DIM))[lane];
        float4 v3 = ((const float4*)(feat + (size_t)s3 * DIM))[lane];
        acc.x += (v0.x + v1.x) + (v2.x + v3.x);
        acc.y += (v0.y + v1.y) + (v2.y + v3.y);
        acc.z += (v0.z + v1.z) + (v2.z + v3.z);
        acc.w += (v0.w + v1.w) + (v2.w + v3.w);
    }
    for (; i < end; i++) {
        int s = g_csr[i];
        float4 v = ((const float4*)(feat + (size_t)s * DIM))[lane];
        acc.x += v.x; acc.y += v.y; acc.z += v.z; acc.w += v.w;
    }
    if (GCN) {
        float di = g_dinv[w];
        acc.x *= di; acc.y *= di; acc.z *= di; acc.w *= di;
    }
    acc.x = tf32r(acc.x); acc.y = tf32r(acc.y);
    acc.z = tf32r(acc.z); acc.w = tf32r(acc.w);
    ((float4*)(out + (size_t)w * DIM))[lane] = acc;
}

// ======== shared GEMM geometry ===========================================
#define A_BYTES 16384           // 128 rows x 32 floats (one 32-K chunk)
#define B_WORDS (32 * 136)      // k x n, stride 136
#define B_BYTES (B_WORDS * 4)   // 17408

// ======== fused GIN MLP: Y = dinv * relu(relu(X@W1+b1)@W2+b2) ============
// Phase 1: X@W1 tile (cp.async staged into first 32KB of TA), t tile written
// to TA (64KB, ldmatrix layout, row stride 512B). Phase 2: t@W2 from TA.
#define TA_BYTES 65536
#define FB0 TA_BYTES
#define FB1 (TA_BYTES + B_BYTES)
#define FS_TOT (TA_BYTES + 2 * B_BYTES)   // 100352

__global__ __launch_bounds__(256, 2)
void k_gin_mlp(const float* __restrict__ X, const float* __restrict__ W1,
               const float* __restrict__ b1v, const float* __restrict__ W2,
               const float* __restrict__ b2v, float* __restrict__ Y, int N) {
    extern __shared__ char sm[];
    const uint32_t smb = smem_u32(sm);
    const int tid  = threadIdx.x;
    const int lane = tid & 31;
    const int wid  = tid >> 5;
    const int wm   = wid & 1;
    const int wn   = wid >> 1;
    const int g    = lane >> 2;
    const int c    = lane & 3;
    const int m0   = blockIdx.x * 128;
    const int sub  = lane >> 3, lrow = lane & 7;

    // ---- staging ----
    auto stage_a = [&](int buf, int kb) {
        uint32_t a_dst = smb + buf * A_BYTES;
#pragma unroll
        for (int j = 0; j < 4; j++) {
            int idx = tid * 4 + j;
            int r = idx >> 3, ch = idx & 7;
            int gm = m0 + r;
            uint32_t d = a_dst + r * 128 + ((ch ^ (r & 7)) << 4);
            cp16(d, X + (size_t)gm * DIM + kb + ch * 4, (gm < N) ? 16u : 0u);
        }
    };
    auto stage_b = [&](const float* W, int buf, int kb) {
        uint32_t b_dst = smb + (buf ? FB1 : FB0);
#pragma unroll
        for (int j = 0; j < 4; j++) {
            int idx = tid * 4 + j;
            int kw = idx >> 5, nc = (idx & 31) * 4;
            cp16(b_dst + (kw * 136 + nc) * 4, W + (size_t)(kb + kw) * DIM + nc, 16u);
        }
    };

    float acc[4][4][4];
#pragma unroll
    for (int mi = 0; mi < 4; mi++)
#pragma unroll
        for (int ni = 0; ni < 4; ni++)
#pragma unroll
            for (int q = 0; q < 4; q++) acc[mi][ni][q] = 0.f;

    // =================== phase 1: X @ W1 ===================
    stage_a(0, 0); stage_b(W1, 0, 0);
    asm volatile("cp.async.commit_group;" ::: "memory");
#pragma unroll
    for (int it = 0; it < 4; it++) {
        if (it < 3) {
            stage_a((it + 1) & 1, (it + 1) * 32);
            stage_b(W1, (it + 1) & 1, (it + 1) * 32);
            asm volatile("cp.async.commit_group;" ::: "memory");
            asm volatile("cp.async.wait_group 1;" ::: "memory");
        } else {
            asm volatile("cp.async.wait_group 0;" ::: "memory");
        }
        __syncthreads();
        const int buf = it & 1;
        const uint32_t abase = smb + buf * A_BYTES;
        const uint32_t* Bp = (const uint32_t*)(sm + (buf ? FB1 : FB0));
#pragma unroll
        for (int ks = 0; ks < 4; ks++) {
            uint32_t a[4][4];
#pragma unroll
            for (int mi = 0; mi < 4; mi++) {
                int r = wm * 64 + mi * 16 + lrow + (sub & 1) * 8;
                int ch = ks * 2 + (sub >> 1);
                uint32_t addr = abase + r * 128 + ((ch ^ (r & 7)) << 4);
                asm volatile(
                    "ldmatrix.sync.aligned.m8n8.x4.shared.b16 {%0,%1,%2,%3}, [%4];"
                    : "=r"(a[mi][0]), "=r"(a[mi][1]), "=r"(a[mi][2]), "=r"(a[mi][3])
                    : "r"(addr));
            }
            uint32_t b[4][2];
            const int k8 = ks * 8;
#pragma unroll
            for (int ni = 0; ni < 4; ni++) {
                int ncol = wn * 32 + ni * 8 + g;
                b[ni][0] = Bp[(k8 + c) * 136 + ncol];
                b[ni][1] = Bp[(k8 + c + 4) * 136 + ncol];
            }
#pragma unroll
            for (int mi = 0; mi < 4; mi++)
#pragma unroll
                for (int ni = 0; ni < 4; ni++)
                    asm volatile(
                        "mma.sync.aligned.m16n8k8.row.col.f32.tf32.tf32.f32 "
                        "{%0,%1,%2,%3}, {%4,%5,%6,%7}, {%8,%9}, {%0,%1,%2,%3};"
                        : "+f"(acc[mi][ni][0]), "+f"(acc[mi][ni][1]),
                          "+f"(acc[mi][ni][2]), "+f"(acc[mi][ni][3])
                        : "r"(a[mi][0]), "r"(a[mi][1]), "r"(a[mi][2]), "r"(a[mi][3]),
                          "r"(b[ni][0]), "r"(b[ni][1]));
        }
        __syncthreads();
    }

    // prefetch W2 chunk 0 while we drain accumulators into the t tile
    stage_b(W2, 0, 0);
    asm volatile("cp.async.commit_group;" ::: "memory");

    // ---- write t = tf32r(relu(acc + b1)) into TA (row stride 512B) ----
#pragma unroll
    for (int ni = 0; ni < 4; ni++) {
        int col = wn * 32 + ni * 8 + 2 * c;
        float bb0 = b1v[col], bb1 = b1v[col + 1];
        int ch = col >> 2;
        int bo = (col & 3) * 4;
#pragma unroll
        for (int mi = 0; mi < 4; mi++) {
            int r0 = wm * 64 + mi * 16 + g;
            int r1 = r0 + 8;
            *(float2*)(sm + r0 * 512 + ((ch ^ (r0 & 7)) << 4) + bo) =
                make_float2(tf32r(fmaxf(acc[mi][ni][0] + bb0, 0.f)),
                            tf32r(fmaxf(acc[mi][ni][1] + bb1, 0.f)));
            *(float2*)(sm + r1 * 512 + ((ch ^ (r1 & 7)) << 4) + bo) =
                make_float2(tf32r(fmaxf(acc[mi][ni][2] + bb0, 0.f)),
                            tf32r(fmaxf(acc[mi][ni][3] + bb1, 0.f)));
            acc[mi][ni][0] = acc[mi][ni][1] = acc[mi][ni][2] = acc[mi][ni][3] = 0.f;
        }
    }
    __syncthreads();

    // =================== phase 2: t @ W2 ===================
#pragma unroll
    for (int it = 0; it < 4; it++) {
        if (it < 3) {
            stage_b(W2, (it + 1) & 1, (it + 1) * 32);
            asm volatile("cp.async.commit_group;" ::: "memory");
            asm volatile("cp.async.wait_group 1;" ::: "memory");
        } else {
            asm volatile("cp.async.wait_group 0;" ::: "memory");
        }
        __syncthreads();
        const uint32_t* Bp = (const uint32_t*)(sm + ((it & 1) ? FB1 : FB0));
#pragma unroll
        for (int ks = 0; ks < 4; ks++) {
            uint32_t a[4][4];
#pragma unroll
            for (int mi = 0; mi < 4; mi++) {
                int r = wm * 64 + mi * 16 + lrow + (sub & 1) * 8;
                int ch = it * 8 + ks * 2 + (sub >> 1);
                uint32_t addr = smb + r * 512 + ((ch ^ (r & 7)) << 4);
                asm volatile(
                    "ldmatrix.sync.aligned.m8n8.x4.shared.b16 {%0,%1,%2,%3}, [%4];"
                    : "=r"(a[mi][0]), "=r"(a[mi][1]), "=r"(a[mi][2]), "=r"(a[mi][3])
                    : "r"(addr));
            }
            uint32_t b[4][2];
            const int k8 = ks * 8;
#pragma unroll
            for (int ni = 0; ni < 4; ni++) {
                int ncol = wn * 32 + ni * 8 + g;
                b[ni][0] = Bp[(k8 + c) * 136 + ncol];
                b[ni][1] = Bp[(k8 + c + 4) * 136 + ncol];
            }
#pragma unroll
            for (int mi = 0; mi < 4; mi++)
#pragma unroll
                for (int ni = 0; ni < 4; ni++)
                    asm volatile(
                        "mma.sync.aligned.m16n8k8.row.col.f32.tf32.tf32.f32 "
                        "{%0,%1,%2,%3}, {%4,%5,%6,%7}, {%8,%9}, {%0,%1,%2,%3};"
                        : "+f"(acc[mi][ni][0]), "+f"(acc[mi][ni][1]),
                          "+f"(acc[mi][ni][2]), "+f"(acc[mi][ni][3])
                        : "r"(a[mi][0]), "r"(a[mi][1]), "r"(a[mi][2]), "r"(a[mi][3]),
                          "r"(b[ni][0]), "r"(b[ni][1]));
        }
        __syncthreads();
    }

    // ---- epilogue: h = dinv * relu(acc + b2) (no rounding; pull1 rounds) ----
#pragma unroll
    for (int ni = 0; ni < 4; ni++) {
        int col = wn * 32 + ni * 8 + 2 * c;
        float bb0 = b2v[col], bb1 = b2v[col + 1];
#pragma unroll
        for (int mi = 0; mi < 4; mi++) {
            int r0 = m0 + wm * 64 + mi * 16 + g;
            int r1 = r0 + 8;
            if (r0 < N) {
                float sc = g_dinv[r0];
                *(float2*)(Y + (size_t)r0 * 128 + col) =
                    make_float2(sc * fmaxf(acc[mi][ni][0] + bb0, 0.f),
                                sc * fmaxf(acc[mi][ni][1] + bb1, 0.f));
            }
            if (r1 < N) {
                float sc = g_dinv[r1];
                *(float2*)(Y + (size_t)r1 * 128 + col) =
                    make_float2(sc * fmaxf(acc[mi][ni][2] + bb0, 0.f),
                                sc * fmaxf(acc[mi][ni][3] + bb1, 0.f));
            }
        }
    }
}

// ======== GCN GEMM with fused pooling (red-add epilogue) =================
#define OFF_A0  0
#define OFF_A1  A_BYTES
#define OFF_B0  (2 * A_BYTES)
#define OFF_B1  (2 * A_BYTES + B_BYTES)
#define SMEM_TOT (2 * A_BYTES + 2 * B_BYTES)   // 67584

__global__ __launch_bounds__(256, 2)
void k_gemm_pool(const float* __restrict__ X, const float* __restrict__ W,
                 const float* __restrict__ bias,
                 const int* __restrict__ batch, float* __restrict__ pool, int N) {
    extern __shared__ char sm[];
    const uint32_t smb = smem_u32(sm);
    const int tid  = threadIdx.x;
    const int lane = tid & 31;
    const int wid  = tid >> 5;
    const int wm   = wid & 1;
    const int wn   = wid >> 1;
    const int g    = lane >> 2;
    const int c    = lane & 3;
    const int m0   = blockIdx.x * 128;
    const int sub  = lane >> 3, lrow = lane & 7;

    auto stage = [&](int buf, int kb) {
        uint32_t a_dst = smb + (buf ? OFF_A1 : OFF_A0);
        uint32_t b_dst = smb + (buf ? OFF_B1 : OFF_B0);
#pragma unroll
        for (int j = 0; j < 4; j++) {
            int idx = tid * 4 + j;
            int r = idx >> 3, ch = idx & 7;
            int gm = m0 + r;
            uint32_t d = a_dst + r * 128 + ((ch ^ (r & 7)) << 4);
            cp16(d, X + (size_t)gm * DIM + kb + ch * 4, (gm < N) ? 16u : 0u);
        }
#pragma unroll
        for (int j = 0; j < 4; j++) {
            int idx = tid * 4 + j;
            int kw = idx >> 5, nc = (idx & 31) * 4;
            cp16(b_dst + (kw * 136 + nc) * 4, W + (size_t)(kb + kw) * DIM + nc, 16u);
        }
        asm volatile("cp.async.commit_group;" ::: "memory");
    };

    float acc[4][4][4];
#pragma unroll
    for (int mi = 0; mi < 4; mi++)
#pragma unroll
        for (int ni = 0; ni < 4; ni++)
#pragma unroll
            for (int q = 0; q < 4; q++) acc[mi][ni][q] = 0.f;

    stage(0, 0);
#pragma unroll
    for (int it = 0; it < 4; it++) {
        if (it < 3) stage((it + 1) & 1, (it + 1) * 32);
        if (it < 3) asm volatile("cp.async.wait_group 1;" ::: "memory");
        else        asm volatile("cp.async.wait_group 0;" ::: "memory");
        __syncthreads();
        const int buf = it & 1;
        const uint32_t abase = smb + (buf ? OFF_A1 : OFF_A0);
        const uint32_t* Bp = (const uint32_t*)(sm + (buf ? OFF_B1 : OFF_B0));
#pragma unroll
        for (int ks = 0; ks < 4; ks++) {
            uint32_t a[4][4];
#pragma unroll
            for (int mi = 0; mi < 4; mi++) {
                int r = wm * 64 + mi * 16 + lrow + (sub & 1) * 8;
                int ch = ks * 2 + (sub >> 1);
                uint32_t addr = abase + r * 128 + ((ch ^ (r & 7)) << 4);
                asm volatile(
                    "ldmatrix.sync.aligned.m8n8.x4.shared.b16 {%0,%1,%2,%3}, [%4];"
                    : "=r"(a[mi][0]), "=r"(a[mi][1]), "=r"(a[mi][2]), "=r"(a[mi][3])
                    : "r"(addr));
            }
            uint32_t b[4][2];
            const int k8 = ks * 8;
#pragma unroll
            for (int ni = 0; ni < 4; ni++) {
                int ncol = wn * 32 + ni * 8 + g;
                b[ni][0] = Bp[(k8 + c) * 136 + ncol];
                b[ni][1] = Bp[(k8 + c + 4) * 136 + ncol];
            }
#pragma unroll
            for (int mi = 0; mi < 4; mi++)
#pragma unroll
                for (int ni = 0; ni < 4; ni++)
                    asm volatile(
                        "mma.sync.aligned.m16n8k8.row.col.f32.tf32.tf32.f32 "
                        "{%0,%1,%2,%3}, {%4,%5,%6,%7}, {%8,%9}, {%0,%1,%2,%3};"
                        : "+f"(acc[mi][ni][0]), "+f"(acc[mi][ni][1]),
                          "+f"(acc[mi][ni][2]), "+f"(acc[mi][ni][3])
                        : "r"(a[mi][0]), "r"(a[mi][1]), "r"(a[mi][2]), "r"(a[mi][3]),
                          "r"(b[ni][0]), "r"(b[ni][1]));
        }
        __syncthreads();
    }

#pragma unroll
    for (int ni = 0; ni < 4; ni++) {
        int col = wn * 32 + ni * 8 + 2 * c;
        float bb0 = bias[col], bb1 = bias[col + 1];
#pragma unroll
        for (int mi = 0; mi < 4; mi++) {
            int r0 = m0 + wm * 64 + mi * 16 + g;
            int r1 = r0 + 8;
            if (r0 < N) {
                float* pp = pool + (size_t)batch[r0] * 128 + col;
                asm volatile("red.global.add.v2.f32 [%0], {%1,%2};"
                             :: "l"(pp), "f"(fmaxf(acc[mi][ni][0] + bb0, 0.f)),
                                "f"(fmaxf(acc[mi][ni][1] + bb1, 0.f)) : "memory");
            }
            if (r1 < N) {
                float* pp = pool + (size_t)batch[r1] * 128 + col;
                asm volatile("red.global.add.v2.f32 [%0], {%1,%2};"
                             :: "l"(pp), "f"(fmaxf(acc[mi][ni][2] + bb0, 0.f)),
                                "f"(fmaxf(acc[mi][ni][3] + bb1, 0.f)) : "memory");
            }
        }
    }
}

// ======== head ===========================================================
__global__ void k_head(const float* __restrict__ w1, const float* __restrict__ b1,
                       const float* __restrict__ w2, const float* __restrict__ b2,
                       float* __restrict__ out) {
    __shared__ float gs[128];
    __shared__ float ts[128];
    int g = blockIdx.x;
    int j = threadIdx.x;
    gs[j] = g_pool[(size_t)g * 128 + j];
    __syncthreads();
    float acc = b1[j];
#pragma unroll 8
    for (int k = 0; k < 128; k++) acc = fmaf(gs[k], w1[(size_t)k * 128 + j], acc);
    ts[j] = fmaxf(acc, 0.f);
    __syncthreads();
    if (j < 32) {
        float o0 = 0.f, o1 = 0.f, o2 = 0.f;
#pragma unroll
        for (int k = j; k < 128; k += 32) {
            float tv = ts[k];
            o0 = fmaf(tv, w2[k * 3 + 0], o0);
            o1 = fmaf(tv, w2[k * 3 + 1], o1);
            o2 = fmaf(tv, w2[k * 3 + 2], o2);
        }
#pragma unroll
        for (int off = 16; off; off >>= 1) {
            o0 += __shfl_down_sync(0xffffffffu, o0, off);
            o1 += __shfl_down_sync(0xffffffffu, o1, off);
            o2 += __shfl_down_sync(0xffffffffu, o2, off);
        }
        if (j == 0) {
            out[g * 3 + 0] = o0 + b2[0];
            out[g * 3 + 1] = o1 + b2[1];
            out[g * 3 + 2] = o2 + b2[2];
        }
    }
}

// ======== launcher =======================================================
extern "C" void kernel_launch(void* const* d_in, const int* in_sizes, int n_in,
                              void* d_out, int out_size) {
    const float* x      = (const float*)d_in[0];
    const int*   ei     = (const int*)d_in[1];
    const int*   batch  = (const int*)d_in[2];
    const float* gin_w1 = (const float*)d_in[3];
    const float* gin_b1 = (const float*)d_in[4];
    const float* gin_w2 = (const float*)d_in[5];
    const float* gin_b2 = (const float*)d_in[6];
    const float* gcn_w  = (const float*)d_in[7];
    const float* gcn_b  = (const float*)d_in[8];
    const float* lin1_w = (const float*)d_in[9];
    const float* lin1_b = (const float*)d_in[10];
    const float* lin2_w = (const float*)d_in[11];
    const float* lin2_b = (const float*)d_in[12];
    float*       out    = (float*)d_out;

    const int N = in_sizes[0] / DIM;       // 100000
    const int E = in_sizes[1] / 2;         // 1600000

    float* agg_p;  cudaGetSymbolAddress((void**)&agg_p,  g_agg);
    float* t_p;    cudaGetSymbolAddress((void**)&t_p,    g_t);
    float* h_p;    cudaGetSymbolAddress((void**)&h_p,    g_h);
    float* pool_p; cudaGetSymbolAddress((void**)&pool_p, g_pool);
    float* wr_p;   cudaGetSymbolAddress((void**)&wr_p,   g_wr);
    int*   cnt_p;  cudaGetSymbolAddress((void**)&cnt_p,  g_cnt);

    static bool attr_done = false;
    if (!attr_done) {
        cudaFuncSetAttribute(k_gin_mlp,   cudaFuncAttributeMaxDynamicSharedMemorySize, FS_TOT);
        cudaFuncSetAttribute(k_gemm_pool, cudaFuncAttributeMaxDynamicSharedMemorySize, SMEM_TOT);
        attr_done = true;
    }

    const int TB = 256;

    // zero cnt + pool via graph memset nodes (not kernel launches)
    cudaMemsetAsync(cnt_p, 0, N_NODES * sizeof(int));
    cudaMemsetAsync(pool_p, 0, N_GRAPHS * DIM * sizeof(float));

    // CSR build
    k_count<<<(E + TB - 1) / TB, TB>>>(ei, E);
    k_scanA<<<NSCAN, SCAN_B>>>();
    k_scanC<<<(N + TB - 1) / TB, TB>>>();
    k_fill<<<(E + TB - 1) / TB, TB>>>(ei, E);

    int pblocks = (N * 32 + TB - 1) / TB;
    // GIN aggregate (pull): agg = tf32r(x + sum x[src])
    k_pull<0><<<pblocks, TB>>>(x, agg_p);

    // tf32-round the three GEMM weights
    k_round_w<<<(3 * DIM * DIM + TB - 1) / TB, TB>>>(gin_w1, gin_w2, gcn_w);

    int gblocks = (N + 127) / 128;          // 782
    // h = dinv * relu(relu(agg@W1+b1)@W2+b2)   (fused GIN MLP)
    k_gin_mlp<<<gblocks, 256, FS_TOT>>>(agg_p, wr_p + 0 * DIM * DIM, gin_b1,
                                        wr_p + 1 * DIM * DIM, gin_b2, h_p, N);

    // GCN aggregate (pull): t = tf32r(dinv * (h + sum h[src]))
    k_pull<1><<<pblocks, TB>>>(h_p, t_p);

    // pool[batch] += relu(t @ gcn_w + gcn_b)
    k_gemm_pool<<<gblocks, 256, SMEM_TOT>>>(t_p, wr_p + 2 * DIM * DIM, gcn_b,
                                            batch, pool_p, N);

    k_head<<<N_GRAPHS, 128>>>(lin1_w, lin1_b, lin2_w, lin2_b, out);
}